// round 10
// baseline (speedup 1.0000x reference)
#include <cuda_runtime.h>

#define TPB 64            // 2 independent warps per CTA
#define IMG_H 512
#define IMG_W 512
#define N_ITERS 140       // per-band row iterations (multiple of 4)
#define N_BLOCKS 1024

__device__ double g_acc = 0.0;
__device__ unsigned int g_count = 0;

// Own-row load (guarded by rowEnd): 2 aligned float4 + optional halo float4.
#define LOAD_OWN(i_, A_, B_, H_)                                              \
    do {                                                                      \
        const int L = rowStart - 4 + (i_);                                    \
        if ((unsigned)L < (unsigned)rowEnd) {                                 \
            const float4* p = base4 + (size_t)L * (IMG_W / 4) + iA;           \
            A_ = __ldg(p); B_ = __ldg(p + 1);                                 \
            H_ = haloAct ? __ldg(p + hOff) : make_float4(0.f, 0.f, 0.f, 0.f); \
        } else {                                                              \
            A_ = B_ = H_ = make_float4(0.f, 0.f, 0.f, 0.f);                   \
        }                                                                     \
    } while (0)

// Reload of row (i_-9) — guard EQUALS the emit-membership of that row, so the
// returned zeros implement the X-window masking exactly. L1-resident (touched
// 9 rows ago).
#define LOAD_RE(i_, RA_, RB_)                                                 \
    do {                                                                      \
        if ((unsigned)((i_) - 13) < 128u) {                                   \
            const int Lr = rowStart - 13 + (i_);                              \
            const float4* p = base4 + (size_t)Lr * (IMG_W / 4) + iA;          \
            RA_ = __ldg(p); RB_ = __ldg(p + 1);                               \
        } else {                                                              \
            RA_ = RB_ = make_float4(0.f, 0.f, 0.f, 0.f);                      \
        }                                                                     \
    } while (0)

// Process one row: h (horizontal 9-sum), X slide (vertical 9-sum of masked x),
// pairing h(j-4)*X(j-4->current), load-time x^2 accumulation + border terms.
#define PROCESS_ROW(i_, SL_, cA_, cB_, cH_, roA_, roB_)                       \
    do {                                                                      \
        float4 vL, vR;                                                        \
        vL.x = __shfl_up_sync(0xffffffffu, cB_.x, 1);                         \
        vL.y = __shfl_up_sync(0xffffffffu, cB_.y, 1);                         \
        vL.z = __shfl_up_sync(0xffffffffu, cB_.z, 1);                         \
        vL.w = __shfl_up_sync(0xffffffffu, cB_.w, 1);                         \
        vR.x = __shfl_down_sync(0xffffffffu, cA_.x, 1);                       \
        vR.y = __shfl_down_sync(0xffffffffu, cA_.y, 1);                       \
        vR.z = __shfl_down_sync(0xffffffffu, cA_.z, 1);                       \
        vR.w = __shfl_down_sync(0xffffffffu, cA_.w, 1);                       \
        if (lane == 0)  vL = cH_;                                             \
        if (lane == 31) vR = cH_;                                             \
        float h0 = ((vL.x + vL.y) + (vL.z + vL.w))                            \
                 + ((cA_.x + cA_.y) + (cA_.z + cA_.w)) + cB_.x;               \
        float h1 = h0 - vL.x + cB_.y;                                         \
        float h2 = h1 - vL.y + cB_.z;                                         \
        float h3 = h2 - vL.z + cB_.w;                                         \
        float h4 = h3 - vL.w + vR.x;                                          \
        float h5 = h4 - cA_.x + vR.y;                                         \
        float h6 = h5 - cA_.y + vR.z;                                         \
        float h7 = h6 - cA_.z + vR.w;                                         \
        const float4 pA = hA[SL_];   /* h of row (i_-4): the pairing row */   \
        const float4 pB = hB[SL_];                                            \
        hA[SL_] = make_float4(h0, h1, h2, h3);                                \
        hB[SL_] = make_float4(h4, h5, h6, h7);                                \
        const float mk = ((unsigned)((i_) - 4) < 128u) ? 1.0f : 0.0f;         \
        float4 xmA, xmB;                                                      \
        xmA.x = mk * cA_.x; xmA.y = mk * cA_.y;                               \
        xmA.z = mk * cA_.z; xmA.w = mk * cA_.w;                               \
        xmB.x = mk * cB_.x; xmB.y = mk * cB_.y;                               \
        xmB.z = mk * cB_.z; xmB.w = mk * cB_.w;                               \
        Xa.x += xmA.x - roA_.x;  Xa.y += xmA.y - roA_.y;                      \
        Xa.z += xmA.z - roA_.z;  Xa.w += xmA.w - roA_.w;                      \
        Xb.x += xmB.x - roB_.x;  Xb.y += xmB.y - roB_.y;                      \
        Xb.z += xmB.z - roB_.z;  Xb.w += xmB.w - roB_.w;                      \
        acc_xs = fmaf(pA.x, Xa.x, acc_xs);                                    \
        acc_xs = fmaf(pA.y, Xa.y, acc_xs);                                    \
        acc_xs = fmaf(pA.z, Xa.z, acc_xs);                                    \
        acc_xs = fmaf(pA.w, Xa.w, acc_xs);                                    \
        acc_xs = fmaf(pB.x, Xb.x, acc_xs);                                    \
        acc_xs = fmaf(pB.y, Xb.y, acc_xs);                                    \
        acc_xs = fmaf(pB.z, Xb.z, acc_xs);                                    \
        acc_xs = fmaf(pB.w, Xb.w, acc_xs);                                    \
        acc_sq = fmaf(xmA.x, cA_.x, acc_sq);                                  \
        acc_sq = fmaf(xmA.y, cA_.y, acc_sq);                                  \
        acc_sq = fmaf(xmA.z, cA_.z, acc_sq);                                  \
        acc_sq = fmaf(xmA.w, cA_.w, acc_sq);                                  \
        acc_sq = fmaf(xmB.x, cB_.x, acc_sq);                                  \
        acc_sq = fmaf(xmB.y, cB_.y, acc_sq);                                  \
        acc_sq = fmaf(xmB.z, cB_.z, acc_sq);                                  \
        acc_sq = fmaf(xmB.w, cB_.w, acc_sq);                                  \
        const float4 xsm = (colhalf == 0) ? xmA : xmB;                        \
        const float4 xsr = (colhalf == 0) ? cA_ : cB_;                        \
        acc_w = fmaf(w4.x * xsm.x, xsr.x, acc_w);                             \
        acc_w = fmaf(w4.y * xsm.y, xsr.y, acc_w);                             \
        acc_w = fmaf(w4.z * xsm.z, xsr.z, acc_w);                             \
        acc_w = fmaf(w4.w * xsm.w, xsr.w, acc_w);                             \
        const int r = rowStart - 4 + (i_);                                    \
        if (((unsigned)r < 4u) | (r > IMG_H - 5)) {  /* uniform, rare */      \
            float rowsq = ((xmA.x * cA_.x + xmA.y * cA_.y)                    \
                         + (xmA.z * cA_.z + xmA.w * cA_.w))                   \
                        + ((xmB.x * cB_.x + xmB.y * cB_.y)                    \
                         + (xmB.z * cB_.z + xmB.w * cB_.w));                  \
            float roww = ((w4.x * xsm.x * xsr.x + w4.y * xsm.y * xsr.y)       \
                        + (w4.z * xsm.z * xsr.z + w4.w * xsm.w * xsr.w));     \
            const float cnth = (float)(min(r, 4) + min(IMG_H - 1 - r, 4) + 1);\
            acc_c = fmaf(9.0f - cnth, fmaf(9.0f, rowsq, -roww), acc_c);       \
        }                                                                     \
    } while (0)

__global__ void __launch_bounds__(TPB, 9) sc_main(const float* __restrict__ img,
                                                  float* __restrict__ out) {
    const int tid  = threadIdx.x;
    const int lane = tid & 31;
    const int wid  = tid >> 5;
    const int plane   = blockIdx.x;
    const int region  = blockIdx.y * 2 + wid;   // 0..7
    const int colhalf = region & 1;
    const int vband   = region >> 1;            // 0..3
    const int rowStart = vband * 128;
    const int rowEnd   = min(IMG_H, rowStart + 132);  // h rows end at rowStart+131

    const float4* base4 = (const float4*)img + (size_t)plane * (IMG_H * (IMG_W / 4));
    const int iA = colhalf * 64 + 2 * lane;

    const bool haloAct = (lane == 0 && colhalf == 1) || (lane == 31 && colhalf == 0);
    const int  hOff    = (lane == 0) ? -1 : 2;

    const int cbase = colhalf * 256 + 8 * lane;
    const int cj = (colhalf == 0) ? cbase : cbase + 4;
    float4 w4;   // 9 - cnt_w per potentially-border column
    w4.x = (float)(max(4 - (cj + 0), 0) + max((cj + 0) - 507, 0));
    w4.y = (float)(max(4 - (cj + 1), 0) + max((cj + 1) - 507, 0));
    w4.z = (float)(max(4 - (cj + 2), 0) + max((cj + 2) - 507, 0));
    w4.w = (float)(max(4 - (cj + 3), 0) + max((cj + 3) - 507, 0));

    // h ring, delay 4, REGISTERS (same-slot read-then-write, static idx)
    float4 hA[4], hB[4];
#pragma unroll
    for (int i = 0; i < 4; i++) {
        hA[i] = make_float4(0.f, 0.f, 0.f, 0.f);
        hB[i] = make_float4(0.f, 0.f, 0.f, 0.f);
    }
    float4 Xa = make_float4(0.f, 0.f, 0.f, 0.f);  // vertical 9-sum of masked x
    float4 Xb = make_float4(0.f, 0.f, 0.f, 0.f);
    float acc_sq = 0.f, acc_xs = 0.f, acc_w = 0.f, acc_c = 0.f;

    // pipeline: rows i, i+1 resident; own-loads for i+2/i+3 issued at pair top
    float4 c0A, c0B, c0H, c1A, c1B, c1H;
    LOAD_OWN(0, c0A, c0B, c0H);
    LOAD_OWN(1, c1A, c1B, c1H);

    for (int it = 0; it < N_ITERS / 4; ++it) {
#pragma unroll
        for (int kk = 0; kk < 2; ++kk) {
            const int i0 = it * 4 + 2 * kk;

            // batched prefetch: next pair's own rows + this pair's reload rows
            float4 n0A, n0B, n0H, n1A, n1B, n1H;
            float4 r0A, r0B, r1A, r1B;
            LOAD_OWN(i0 + 2, n0A, n0B, n0H);
            LOAD_OWN(i0 + 3, n1A, n1B, n1H);
            LOAD_RE(i0,     r0A, r0B);
            LOAD_RE(i0 + 1, r1A, r1B);

            PROCESS_ROW(i0,     (2 * kk)     & 3, c0A, c0B, c0H, r0A, r0B);
            PROCESS_ROW(i0 + 1, (2 * kk + 1) & 3, c1A, c1B, c1H, r1A, r1B);

            c0A = n0A; c0B = n0B; c0H = n0H;
            c1A = n1A; c1B = n1B; c1H = n1H;
        }
    }

    // total = 162*sum(x^2) - 2*sum(h*X) - [9*acc_w + acc_c]
    float acc = fmaf(162.0f, acc_sq, fmaf(-2.0f, acc_xs, -fmaf(9.0f, acc_w, acc_c)));

    // warp reduce -> CTA reduce -> one atomic per CTA; last CTA finalizes
#pragma unroll
    for (int off = 16; off; off >>= 1) acc += __shfl_down_sync(0xffffffffu, acc, off);
    __shared__ float wsum[2];
    if (lane == 0) wsum[wid] = acc;
    __syncthreads();
    if (tid == 0) {
        atomicAdd(&g_acc, (double)(wsum[0] + wsum[1]));
        __threadfence();
        unsigned int t = atomicAdd(&g_count, 1u);
        if (t == N_BLOCKS - 1) {
            out[0] = (float)(g_acc * 0.125);   // mean over batch of 8
            g_acc = 0.0;
            g_count = 0u;
        }
    }
}

extern "C" void kernel_launch(void* const* d_in, const int* in_sizes, int n_in,
                              void* d_out, int out_size) {
    const float* img = (const float*)d_in[0];
    dim3 grid(256, 4);          // 1024 CTAs = N_BLOCKS
    sc_main<<<grid, TPB>>>(img, (float*)d_out);
}

// round 11
// speedup vs baseline: 2.2362x; 2.2362x over previous
#include <cuda_runtime.h>

#define TPB 64            // 2 independent warps per CTA
#define IMG_H 512
#define IMG_W 512
#define N_ITERS 80        // 64 emit rows + 8 halo + ring alignment (mult of 10)
#define N_BLOCKS 2048     // grid (256 x 8)

__device__ double g_acc = 0.0;
__device__ unsigned int g_count = 0;

// Load row (guarded): batched at iteration top for MLP.
#define LOAD_ROW(L_, A_, B_, H_)                                              \
    do {                                                                      \
        const int L = (L_);                                                   \
        if ((unsigned)L < (unsigned)rowEnd) {                                 \
            const float4* p = base4 + (size_t)L * (IMG_W / 4) + iA;           \
            A_ = __ldg(p); B_ = __ldg(p + 1);                                 \
            H_ = haloAct ? __ldg(p + hOff) : make_float4(0.f, 0.f, 0.f, 0.f); \
        } else {                                                              \
            A_ = B_ = H_ = make_float4(0.f, 0.f, 0.f, 0.f);                   \
        }                                                                     \
    } while (0)

// Process one row (absolute iteration index i_, ring slots static per call).
#define PROCESS_ROW(i_, KS_, KX_, cA_, cB_, cH_)                              \
    do {                                                                      \
        float4 vL, vR;                                                        \
        vL.x = __shfl_up_sync(0xffffffffu, cB_.x, 1);                         \
        vL.y = __shfl_up_sync(0xffffffffu, cB_.y, 1);                         \
        vL.z = __shfl_up_sync(0xffffffffu, cB_.z, 1);                         \
        vL.w = __shfl_up_sync(0xffffffffu, cB_.w, 1);                         \
        vR.x = __shfl_down_sync(0xffffffffu, cA_.x, 1);                       \
        vR.y = __shfl_down_sync(0xffffffffu, cA_.y, 1);                       \
        vR.z = __shfl_down_sync(0xffffffffu, cA_.z, 1);                       \
        vR.w = __shfl_down_sync(0xffffffffu, cA_.w, 1);                       \
        if (lane == 0)  vL = cH_;                                             \
        if (lane == 31) vR = cH_;                                             \
        float h0 = ((vL.x + vL.y) + (vL.z + vL.w))                            \
                 + ((cA_.x + cA_.y) + (cA_.z + cA_.w)) + cB_.x;               \
        float h1 = h0 - vL.x + cB_.y;                                         \
        float h2 = h1 - vL.y + cB_.z;                                         \
        float h3 = h2 - vL.z + cB_.w;                                         \
        float h4 = h3 - vL.w + vR.x;                                          \
        float h5 = h4 - cA_.x + vR.y;                                         \
        float h6 = h5 - cA_.y + vR.z;                                         \
        float h7 = h6 - cA_.z + vR.w;                                         \
        const float4 oA = ringA[((KS_) + 1) % 10][tid];                       \
        const float4 oB = ringB[((KS_) + 1) % 10][tid];                       \
        Sa.x += h0 - oA.x;  Sa.y += h1 - oA.y;                                \
        Sa.z += h2 - oA.z;  Sa.w += h3 - oA.w;                                \
        Sb.x += h4 - oB.x;  Sb.y += h5 - oB.y;                                \
        Sb.z += h6 - oB.z;  Sb.w += h7 - oB.w;                                \
        ringA[(KS_) % 10][tid] = make_float4(h0, h1, h2, h3);                 \
        ringB[(KS_) % 10][tid] = make_float4(h4, h5, h6, h7);                 \
        const float4 xa = xrA[((KX_) + 1) % 5];                               \
        const float4 xb = xrB[((KX_) + 1) % 5];                               \
        xrA[(KX_) % 5] = cA_;                                                 \
        xrB[(KX_) % 5] = cB_;                                                 \
        if ((i_) >= 8 && (i_) < 72) {                                         \
            acc_sq = fmaf(xa.x, xa.x, acc_sq);                                \
            acc_sq = fmaf(xa.y, xa.y, acc_sq);                                \
            acc_sq = fmaf(xa.z, xa.z, acc_sq);                                \
            acc_sq = fmaf(xa.w, xa.w, acc_sq);                                \
            acc_sq = fmaf(xb.x, xb.x, acc_sq);                                \
            acc_sq = fmaf(xb.y, xb.y, acc_sq);                                \
            acc_sq = fmaf(xb.z, xb.z, acc_sq);                                \
            acc_sq = fmaf(xb.w, xb.w, acc_sq);                                \
            acc_xs = fmaf(xa.x, Sa.x, acc_xs);                                \
            acc_xs = fmaf(xa.y, Sa.y, acc_xs);                                \
            acc_xs = fmaf(xa.z, Sa.z, acc_xs);                                \
            acc_xs = fmaf(xa.w, Sa.w, acc_xs);                                \
            acc_xs = fmaf(xb.x, Sb.x, acc_xs);                                \
            acc_xs = fmaf(xb.y, Sb.y, acc_xs);                                \
            acc_xs = fmaf(xb.z, Sb.z, acc_xs);                                \
            acc_xs = fmaf(xb.w, Sb.w, acc_xs);                                \
            const float4 xs = (colhalf == 0) ? xa : xb;                       \
            acc_w = fmaf(w4.x * xs.x, xs.x, acc_w);                           \
            acc_w = fmaf(w4.y * xs.y, xs.y, acc_w);                           \
            acc_w = fmaf(w4.z * xs.z, xs.z, acc_w);                           \
            acc_w = fmaf(w4.w * xs.w, xs.w, acc_w);                           \
            const int r = rowStart - 8 + (i_);                                \
            const bool rowB = (r < 4) | (r > IMG_H - 5);                      \
            if (rowB) {                                                       \
                float rowsq = 0.f, roww = 0.f;                                \
                rowsq += xa.x * xa.x + xa.y * xa.y + xa.z * xa.z + xa.w * xa.w; \
                rowsq += xb.x * xb.x + xb.y * xb.y + xb.z * xb.z + xb.w * xb.w; \
                roww = fmaf(w4.x * xs.x, xs.x, roww);                         \
                roww = fmaf(w4.y * xs.y, xs.y, roww);                         \
                roww = fmaf(w4.z * xs.z, xs.z, roww);                         \
                roww = fmaf(w4.w * xs.w, xs.w, roww);                         \
                const float cnth = (float)(min(r, 4) + min(IMG_H - 1 - r, 4) + 1); \
                acc_c = fmaf(9.0f - cnth, fmaf(9.0f, rowsq, -roww), acc_c);   \
            }                                                                 \
        }                                                                     \
    } while (0)

__global__ void __launch_bounds__(TPB, 8) sc_main(const float* __restrict__ img,
                                                  float* __restrict__ out) {
    const int tid  = threadIdx.x;
    const int lane = tid & 31;
    const int wid  = tid >> 5;
    const int plane   = blockIdx.x;
    const int region  = blockIdx.y * 2 + wid;   // 0..15
    const int colhalf = region & 1;
    const int vband   = region >> 1;            // 0..7
    const int rowStart = vband * 64;
    const int rowEnd   = min(IMG_H, rowStart + 68);   // last h-row needed + 1

    const float4* base4 = (const float4*)img + (size_t)plane * (IMG_H * (IMG_W / 4));
    const int iA = colhalf * 64 + 2 * lane;

    const bool haloAct = (lane == 0 && colhalf == 1) || (lane == 31 && colhalf == 0);
    const int  hOff    = (lane == 0) ? -1 : 2;

    const int cbase = colhalf * 256 + 8 * lane;
    const int cj = (colhalf == 0) ? cbase : cbase + 4;
    float4 w4;
    w4.x = (float)(max(4 - (cj + 0), 0) + max((cj + 0) - 507, 0));
    w4.y = (float)(max(4 - (cj + 1), 0) + max((cj + 1) - 507, 0));
    w4.z = (float)(max(4 - (cj + 2), 0) + max((cj + 2) - 507, 0));
    w4.w = (float)(max(4 - (cj + 3), 0) + max((cj + 3) - 507, 0));

    __shared__ float4 ringA[10][TPB];
    __shared__ float4 ringB[10][TPB];
#pragma unroll
    for (int i = 0; i < 10; i++) {
        ringA[i][tid] = make_float4(0.f, 0.f, 0.f, 0.f);
        ringB[i][tid] = make_float4(0.f, 0.f, 0.f, 0.f);
    }

    float4 xrA[5], xrB[5];
#pragma unroll
    for (int i = 0; i < 5; i++) {
        xrA[i] = make_float4(0.f, 0.f, 0.f, 0.f);
        xrB[i] = make_float4(0.f, 0.f, 0.f, 0.f);
    }
    float4 Sa = make_float4(0.f, 0.f, 0.f, 0.f);
    float4 Sb = make_float4(0.f, 0.f, 0.f, 0.f);
    float acc_sq = 0.f, acc_xs = 0.f, acc_w = 0.f, acc_c = 0.f;

    // pipeline: rows i and i+1 resident, rows i+2/i+3 loaded at iteration top
    float4 c0A, c0B, c0H, c1A, c1B, c1H;
    LOAD_ROW(rowStart - 4, c0A, c0B, c0H);
    LOAD_ROW(rowStart - 3, c1A, c1B, c1H);

    for (int it = 0; it < N_ITERS / 10; ++it) {
#pragma unroll
        for (int kk = 0; kk < 5; ++kk) {
            const int i0 = it * 10 + 2 * kk;

            // batched prefetch of the next row pair (front-batched LDGs)
            float4 n0A, n0B, n0H, n1A, n1B, n1H;
            LOAD_ROW(rowStart - 2 + i0, n0A, n0B, n0H);
            LOAD_ROW(rowStart - 1 + i0, n1A, n1B, n1H);

            PROCESS_ROW(i0,     2 * kk,     2 * kk,     c0A, c0B, c0H);
            PROCESS_ROW(i0 + 1, 2 * kk + 1, 2 * kk + 1, c1A, c1B, c1H);

            c0A = n0A; c0B = n0B; c0H = n0H;
            c1A = n1A; c1B = n1B; c1H = n1H;
        }
    }

    float acc = fmaf(162.0f, acc_sq, fmaf(-2.0f, acc_xs, -fmaf(9.0f, acc_w, acc_c)));

    // warp reduce -> CTA reduce -> one atomic per CTA; last CTA finalizes
#pragma unroll
    for (int off = 16; off; off >>= 1) acc += __shfl_down_sync(0xffffffffu, acc, off);
    __shared__ float wsum[2];
    if (lane == 0) wsum[wid] = acc;
    __syncthreads();
    if (tid == 0) {
        atomicAdd(&g_acc, (double)(wsum[0] + wsum[1]));
        __threadfence();
        unsigned int t = atomicAdd(&g_count, 1u);
        if (t == N_BLOCKS - 1) {
            out[0] = (float)(g_acc * 0.125);   // mean over batch of 8
            g_acc = 0.0;
            g_count = 0u;
        }
    }
}

extern "C" void kernel_launch(void* const* d_in, const int* in_sizes, int n_in,
                              void* d_out, int out_size) {
    const float* img = (const float*)d_in[0];
    dim3 grid(256, 8);          // 2048 CTAs = N_BLOCKS
    sc_main<<<grid, TPB>>>(img, (float*)d_out);
}